// round 6
// baseline (speedup 1.0000x reference)
#include <cuda_runtime.h>
#include <cuda_fp16.h>
#include <cstdint>

#define NN 50000
#define D  128
#define KDIM 256
#define BM 128
#define EMAX 640000
#define SCAN_BLOCKS 196   // ceil(50000/256)

// Scratch: __device__ globals (no allocation allowed).
__device__ __align__(128) float  g_agg[(size_t)NN * D];   // MEAN (fp32)
__device__ __align__(128) __half g_xh [(size_t)NN * D];   // x in fp16
__device__ __align__(128) __half g_h1h[(size_t)NN * D];   // h1 in fp16
__device__ __align__(128) int    g_src[EMAX];
__device__ __align__(128) int    g_dst[EMAX];
__device__ __align__(128) int    g_cnt[NN];
__device__ __align__(128) int    g_rowptr[NN + 1];
__device__ __align__(128) int    g_col[EMAX];
__device__ __align__(128) int    g_bsum[256];
__device__ int g_is64;

// ---------------------------------------------------------------------------
__global__ void k_detect(const int* __restrict__ ei32, int n32) {
    __shared__ int any_nz;
    if (threadIdx.x == 0) any_nz = 0;
    __syncthreads();
    int limit = n32 < 8192 ? n32 : 8192;
    int found = 0;
    for (int i = threadIdx.x * 2 + 1; i < limit; i += blockDim.x * 2)
        if (ei32[i] != 0) { found = 1; break; }
    if (found) atomicOr(&any_nz, 1);
    __syncthreads();
    if (threadIdx.x == 0) g_is64 = any_nz ? 0 : 1;
}

__global__ void k_zerocnt() {
    int i = blockIdx.x * 256 + threadIdx.x;
    if (i < NN) g_cnt[i] = 0;
}

// Decode edge list once (int64 or int32) AND build the degree histogram.
__global__ void k_decode(const void* __restrict__ ei, int E) {
    int e = blockIdx.x * blockDim.x + threadIdx.x;
    if (e >= E) return;
    int s, d;
    if (g_is64) {
        s = (int)((const long long*)ei)[e];
        d = (int)((const long long*)ei)[E + e];
    } else {
        s = ((const int*)ei)[e];
        d = ((const int*)ei)[E + e];
    }
    g_src[e] = s;
    g_dst[e] = d;
    atomicAdd(&g_cnt[d], 1);
}

// x (fp32) -> g_xh (fp16). 8 elements per thread.
__global__ void k_tohalf(const float* __restrict__ x) {
    long long i = (long long)blockIdx.x * blockDim.x + threadIdx.x;
    long long tot8 = (long long)NN * D / 8;
    if (i >= tot8) return;
    const float4* p = reinterpret_cast<const float4*>(x) + i * 2;
    float4 a = p[0], b = p[1];
    __half2 h0 = __floats2half2_rn(a.x, a.y);
    __half2 h1 = __floats2half2_rn(a.z, a.w);
    __half2 h2 = __floats2half2_rn(b.x, b.y);
    __half2 h3 = __floats2half2_rn(b.z, b.w);
    uint4 o;
    o.x = *reinterpret_cast<uint32_t*>(&h0);
    o.y = *reinterpret_cast<uint32_t*>(&h1);
    o.z = *reinterpret_cast<uint32_t*>(&h2);
    o.w = *reinterpret_cast<uint32_t*>(&h3);
    reinterpret_cast<uint4*>(g_xh)[i] = o;
}

// Exclusive scan over g_cnt -> g_rowptr (3 stages).
__global__ void k_scan1() {
    __shared__ int sh[256];
    int gid = blockIdx.x * 256 + threadIdx.x;
    int v = (gid < NN) ? g_cnt[gid] : 0;
    sh[threadIdx.x] = v;
    __syncthreads();
    for (int off = 1; off < 256; off <<= 1) {
        int t = (threadIdx.x >= off) ? sh[threadIdx.x - off] : 0;
        __syncthreads();
        sh[threadIdx.x] += t;
        __syncthreads();
    }
    if (gid < NN) g_rowptr[gid] = sh[threadIdx.x] - v;
    if (threadIdx.x == 255) g_bsum[blockIdx.x] = sh[255];
}

__global__ void k_scan2(int nb) {
    __shared__ int sh[256];
    int v = (threadIdx.x < nb) ? g_bsum[threadIdx.x] : 0;
    sh[threadIdx.x] = v;
    __syncthreads();
    for (int off = 1; off < 256; off <<= 1) {
        int t = (threadIdx.x >= off) ? sh[threadIdx.x - off] : 0;
        __syncthreads();
        sh[threadIdx.x] += t;
        __syncthreads();
    }
    if (threadIdx.x < nb) g_bsum[threadIdx.x] = sh[threadIdx.x] - v;
}

__global__ void k_scan3(int E) {
    int gid = blockIdx.x * 256 + threadIdx.x;
    if (gid < NN) {
        int r = g_rowptr[gid] + g_bsum[blockIdx.x];
        g_rowptr[gid] = r;
        g_cnt[gid] = r;          // cursor for fill
    }
    if (gid == 0) g_rowptr[NN] = E;
}

__global__ void k_fill(int E) {
    int e = blockIdx.x * blockDim.x + threadIdx.x;
    if (e < E) {
        int idx = atomicAdd(&g_cnt[g_dst[e]], 1);
        g_col[idx] = g_src[e];
    }
}

// ---------------------------------------------------------------------------
// CSR gather-aggregate over fp16 features, fp32 accumulation.
// One warp per node; lane owns 4 columns (uint2 = 4 halves per row).
// ---------------------------------------------------------------------------
__global__ __launch_bounds__(256) void k_gather(int use_h1) {
    int node = blockIdx.x * 8 + (threadIdx.x >> 5);
    if (node >= NN) return;
    int lane = threadIdx.x & 31;
    const __half* f = use_h1 ? g_h1h : g_xh;
    int beg = g_rowptr[node], end = g_rowptr[node + 1];
    float4 acc = make_float4(0.f, 0.f, 0.f, 0.f);
    int j = beg;
    for (; j + 1 < end; j += 2) {
        int s0 = g_col[j], s1 = g_col[j + 1];
        uint2 u0 = reinterpret_cast<const uint2*>(f + (size_t)s0 * D)[lane];
        uint2 u1 = reinterpret_cast<const uint2*>(f + (size_t)s1 * D)[lane];
        float2 a0 = __half22float2(*reinterpret_cast<__half2*>(&u0.x));
        float2 a1 = __half22float2(*reinterpret_cast<__half2*>(&u0.y));
        float2 b0 = __half22float2(*reinterpret_cast<__half2*>(&u1.x));
        float2 b1 = __half22float2(*reinterpret_cast<__half2*>(&u1.y));
        acc.x += a0.x + b0.x; acc.y += a0.y + b0.y;
        acc.z += a1.x + b1.x; acc.w += a1.y + b1.y;
    }
    if (j < end) {
        int s0 = g_col[j];
        uint2 u0 = reinterpret_cast<const uint2*>(f + (size_t)s0 * D)[lane];
        float2 a0 = __half22float2(*reinterpret_cast<__half2*>(&u0.x));
        float2 a1 = __half22float2(*reinterpret_cast<__half2*>(&u0.y));
        acc.x += a0.x; acc.y += a0.y; acc.z += a1.x; acc.w += a1.y;
    }
    float inv = 1.0f / fmaxf((float)(end - beg), 1.0f);
    acc.x *= inv; acc.y *= inv; acc.z *= inv; acc.w *= inv;
    // lane owns columns [lane*4, lane*4+4)
    *reinterpret_cast<float4*>(g_agg + (size_t)node * D + lane * 4) = acc;
}

// ---------------------------------------------------------------------------
// tf32 tensor-core fused SAGE GEMM:
//   out = relu( mean @ Wl + xh @ Wr + b ),  A = [g_agg | fp16 features]
// BM=128 rows/block, BN=128, BK=16, 8 warps, warp tile 64x32.
// SMEM stride 20 -> conflict-free fragment loads.
// ---------------------------------------------------------------------------
__device__ __forceinline__ uint32_t to_tf32(float f) {
    uint32_t r;
    asm("cvt.rna.tf32.f32 %0, %1;" : "=r"(r) : "f"(f));
    return r;
}

__global__ __launch_bounds__(256) void k_gemm(
    const float* __restrict__ Wl,
    const float* __restrict__ Wr,
    const float* __restrict__ bias,
    float* __restrict__ outbuf,
    int in_from_h1, int out_to_h1)
{
    __shared__ uint32_t As[128][20];
    __shared__ uint32_t Bs[128][20];

    const int tid  = threadIdx.x;
    const int wid  = tid >> 5;
    const int lane = tid & 31;
    const int grp  = lane >> 2;
    const int tig  = lane & 3;
    const int warpRow = (wid >> 2) * 64;
    const int warpCol = (wid & 3) * 32;
    const int rowBase = blockIdx.x * BM;
    const __half* xh = in_from_h1 ? g_h1h : g_xh;

    float acc[4][4][4];
#pragma unroll
    for (int mt = 0; mt < 4; mt++)
#pragma unroll
        for (int nt = 0; nt < 4; nt++)
#pragma unroll
            for (int q = 0; q < 4; q++) acc[mt][nt][q] = 0.f;

    const int arow  = tid >> 1;
    const int akloc = (tid & 1) * 8;

    for (int kb = 0; kb < KDIM / 16; kb++) {
        const int k0 = kb * 16;

        // ---- stage A (128 rows x 16 k)
        {
            int grow = rowBase + arow;
            float v[8];
            if (grow < NN) {
                int kg = k0 + akloc;
                if (k0 < D) {
                    const float4* p = reinterpret_cast<const float4*>(
                        &g_agg[(size_t)grow * D + kg]);
                    float4 u0 = p[0], u1 = p[1];
                    v[0]=u0.x; v[1]=u0.y; v[2]=u0.z; v[3]=u0.w;
                    v[4]=u1.x; v[5]=u1.y; v[6]=u1.z; v[7]=u1.w;
                } else {
                    uint4 u = *reinterpret_cast<const uint4*>(
                        &xh[(size_t)grow * D + (kg - D)]);
                    float2 f0 = __half22float2(*reinterpret_cast<__half2*>(&u.x));
                    float2 f1 = __half22float2(*reinterpret_cast<__half2*>(&u.y));
                    float2 f2 = __half22float2(*reinterpret_cast<__half2*>(&u.z));
                    float2 f3 = __half22float2(*reinterpret_cast<__half2*>(&u.w));
                    v[0]=f0.x; v[1]=f0.y; v[2]=f1.x; v[3]=f1.y;
                    v[4]=f2.x; v[5]=f2.y; v[6]=f3.x; v[7]=f3.y;
                }
            } else {
#pragma unroll
                for (int j = 0; j < 8; j++) v[j] = 0.f;
            }
            uint2* dstp = reinterpret_cast<uint2*>(&As[arow][akloc]);
#pragma unroll
            for (int j = 0; j < 4; j++)
                dstp[j] = make_uint2(to_tf32(v[2*j]), to_tf32(v[2*j+1]));
        }

        // ---- stage B transposed: Bs[col][k] from W[k][col]
#pragma unroll
        for (int it = 0; it < 2; it++) {
            int lin = tid + it * 256;
            int kk  = lin >> 5;
            int c4  = (lin & 31) * 4;
            int kg  = k0 + kk;
            const float* wsrc = (kg < D) ? (Wl + (size_t)kg * D + c4)
                                         : (Wr + (size_t)(kg - D) * D + c4);
            float4 u = *reinterpret_cast<const float4*>(wsrc);
            Bs[c4 + 0][kk] = to_tf32(u.x);
            Bs[c4 + 1][kk] = to_tf32(u.y);
            Bs[c4 + 2][kk] = to_tf32(u.z);
            Bs[c4 + 3][kk] = to_tf32(u.w);
        }
        __syncthreads();

#pragma unroll
        for (int ks = 0; ks < 2; ks++) {
            const int kb8 = ks * 8;
            uint32_t a[4][4], b[4][2];
#pragma unroll
            for (int mt = 0; mt < 4; mt++) {
                int r0 = warpRow + mt * 16;
                a[mt][0] = As[r0 + grp    ][kb8 + tig];
                a[mt][1] = As[r0 + grp + 8][kb8 + tig];
                a[mt][2] = As[r0 + grp    ][kb8 + tig + 4];
                a[mt][3] = As[r0 + grp + 8][kb8 + tig + 4];
            }
#pragma unroll
            for (int nt = 0; nt < 4; nt++) {
                int cn = warpCol + nt * 8 + grp;
                b[nt][0] = Bs[cn][kb8 + tig];
                b[nt][1] = Bs[cn][kb8 + tig + 4];
            }
#pragma unroll
            for (int mt = 0; mt < 4; mt++)
#pragma unroll
                for (int nt = 0; nt < 4; nt++) {
                    asm volatile(
                        "mma.sync.aligned.m16n8k8.row.col.f32.tf32.tf32.f32 "
                        "{%0,%1,%2,%3}, {%4,%5,%6,%7}, {%8,%9}, {%0,%1,%2,%3};\n"
                        : "+f"(acc[mt][nt][0]), "+f"(acc[mt][nt][1]),
                          "+f"(acc[mt][nt][2]), "+f"(acc[mt][nt][3])
                        : "r"(a[mt][0]), "r"(a[mt][1]), "r"(a[mt][2]), "r"(a[mt][3]),
                          "r"(b[nt][0]), "r"(b[nt][1]));
                }
        }
        __syncthreads();
    }

    // ---- epilogue: + bias, relu; store fp16 to g_h1h OR fp32 to outbuf
#pragma unroll
    for (int nt = 0; nt < 4; nt++) {
        int c = warpCol + nt * 8 + 2 * tig;
        float b0 = bias[c], b1 = bias[c + 1];
#pragma unroll
        for (int mt = 0; mt < 4; mt++) {
            int r = rowBase + warpRow + mt * 16 + grp;
            float v0 = fmaxf(acc[mt][nt][0] + b0, 0.f);
            float v1 = fmaxf(acc[mt][nt][1] + b1, 0.f);
            float v2 = fmaxf(acc[mt][nt][2] + b0, 0.f);
            float v3 = fmaxf(acc[mt][nt][3] + b1, 0.f);
            if (out_to_h1) {
                if (r < NN)
                    *reinterpret_cast<__half2*>(&g_h1h[(size_t)r * D + c]) =
                        __floats2half2_rn(v0, v1);
                if (r + 8 < NN)
                    *reinterpret_cast<__half2*>(&g_h1h[(size_t)(r + 8) * D + c]) =
                        __floats2half2_rn(v2, v3);
            } else {
                if (r < NN)
                    *reinterpret_cast<float2*>(&outbuf[(size_t)r * D + c]) =
                        make_float2(v0, v1);
                if (r + 8 < NN)
                    *reinterpret_cast<float2*>(&outbuf[(size_t)(r + 8) * D + c]) =
                        make_float2(v2, v3);
            }
        }
    }
}

// ---------------------------------------------------------------------------
extern "C" void kernel_launch(void* const* d_in, const int* in_sizes, int n_in,
                              void* d_out, int out_size) {
    const float* x   = (const float*)d_in[0];
    const void*  ei  = d_in[1];
    const float* W1l = (const float*)d_in[2];
    const float* b1  = (const float*)d_in[3];
    const float* W1r = (const float*)d_in[4];
    const float* W2l = (const float*)d_in[5];
    const float* b2  = (const float*)d_in[6];
    const float* W2r = (const float*)d_in[7];
    float*       out = (float*)d_out;

    const int E = in_sizes[1] / 2;
    const int eblocks = (E + 255) / 256;
    const int gemmBlocks = (NN + BM - 1) / BM;
    const int gatherBlocks = (NN + 7) / 8;
    const int halfBlocks = (int)(((long long)NN * D / 8 + 255) / 256);

    k_detect<<<1, 256>>>((const int*)ei, in_sizes[1]);
    k_zerocnt<<<SCAN_BLOCKS, 256>>>();
    k_decode<<<eblocks, 256>>>(ei, E);          // decode + histogram
    k_tohalf<<<halfBlocks, 256>>>(x);

    // CSR build
    k_scan1<<<SCAN_BLOCKS, 256>>>();
    k_scan2<<<1, 256>>>(SCAN_BLOCKS);
    k_scan3<<<SCAN_BLOCKS, 256>>>(E);
    k_fill<<<eblocks, 256>>>(E);

    // Layer 1
    k_gather<<<gatherBlocks, 256>>>(0);
    k_gemm<<<gemmBlocks, 256>>>(W1l, W1r, b1, out, 0, 1);   // -> g_h1h (fp16)

    // Layer 2
    k_gather<<<gatherBlocks, 256>>>(1);
    k_gemm<<<gemmBlocks, 256>>>(W2l, W2r, b2, out, 1, 0);   // -> d_out
}

// round 7
// speedup vs baseline: 1.1809x; 1.1809x over previous
#include <cuda_runtime.h>
#include <cstdint>

#define NN 50000
#define D  128
#define KDIM 256
#define BM 128
#define EMAX 640000
#define SCAN_BLOCKS 196   // ceil(50000/256)

// Scratch: __device__ globals (no allocation allowed).
__device__ __align__(128) float g_agg[(size_t)NN * D];   // MEAN after gather
__device__ __align__(128) float g_h1 [(size_t)NN * D];
__device__ __align__(128) int   g_cnt[NN];        // histogram, then fill cursor
__device__ __align__(128) int   g_rowptr[NN + 1];
__device__ __align__(128) int   g_col[EMAX];      // src ids grouped by dst
__device__ __align__(128) int   g_bsum[256];
__device__ int g_is64;

// ---------------------------------------------------------------------------
// Init: zero g_cnt (all blocks); block 0 also probes edge_index dtype
// (int64 node ids < 2^31 -> all odd 32-bit words are 0).
// ---------------------------------------------------------------------------
__global__ void k_init(const int* __restrict__ ei32, int n32) {
    int gid = blockIdx.x * 256 + threadIdx.x;
    if (gid < NN) g_cnt[gid] = 0;
    if (blockIdx.x == 0) {
        __shared__ int any_nz;
        if (threadIdx.x == 0) any_nz = 0;
        __syncthreads();
        int limit = n32 < 8192 ? n32 : 8192;
        int found = 0;
        for (int i = threadIdx.x * 2 + 1; i < limit; i += 512)
            if (ei32[i] != 0) { found = 1; break; }
        if (found) atomicOr(&any_nz, 1);
        __syncthreads();
        if (threadIdx.x == 0) g_is64 = any_nz ? 0 : 1;
    }
}

__device__ __forceinline__ int eidx(const void* ei, int i) {
    return g_is64 ? (int)((const long long*)ei)[i] : ((const int*)ei)[i];
}

__global__ void k_hist(const void* __restrict__ ei, int E) {
    int e = blockIdx.x * blockDim.x + threadIdx.x;
    if (e < E) atomicAdd(&g_cnt[eidx(ei, E + e)], 1);
}

// Exclusive scan over g_cnt -> g_rowptr (3 stages).
__global__ void k_scan1() {
    __shared__ int sh[256];
    int gid = blockIdx.x * 256 + threadIdx.x;
    int v = (gid < NN) ? g_cnt[gid] : 0;
    sh[threadIdx.x] = v;
    __syncthreads();
    for (int off = 1; off < 256; off <<= 1) {
        int t = (threadIdx.x >= off) ? sh[threadIdx.x - off] : 0;
        __syncthreads();
        sh[threadIdx.x] += t;
        __syncthreads();
    }
    if (gid < NN) g_rowptr[gid] = sh[threadIdx.x] - v;
    if (threadIdx.x == 255) g_bsum[blockIdx.x] = sh[255];
}

__global__ void k_scan2(int nb) {
    __shared__ int sh[256];
    int v = (threadIdx.x < nb) ? g_bsum[threadIdx.x] : 0;
    sh[threadIdx.x] = v;
    __syncthreads();
    for (int off = 1; off < 256; off <<= 1) {
        int t = (threadIdx.x >= off) ? sh[threadIdx.x - off] : 0;
        __syncthreads();
        sh[threadIdx.x] += t;
        __syncthreads();
    }
    if (threadIdx.x < nb) g_bsum[threadIdx.x] = sh[threadIdx.x] - v;
}

__global__ void k_scan3(int E) {
    int gid = blockIdx.x * 256 + threadIdx.x;
    if (gid < NN) {
        int r = g_rowptr[gid] + g_bsum[blockIdx.x];
        g_rowptr[gid] = r;
        g_cnt[gid] = r;          // cursor for fill
    }
    if (gid == 0) g_rowptr[NN] = E;
}

__global__ void k_fill(const void* __restrict__ ei, int E) {
    int e = blockIdx.x * blockDim.x + threadIdx.x;
    if (e < E) {
        int s = eidx(ei, e);
        int d = eidx(ei, E + e);
        int idx = atomicAdd(&g_cnt[d], 1);
        g_col[idx] = s;
    }
}

// ---------------------------------------------------------------------------
// CSR gather-aggregate: one warp per node, lane owns one float4 column slice.
// Unroll x4 for MLP (4 independent LDG.128 in flight per warp).
// ---------------------------------------------------------------------------
__global__ __launch_bounds__(256) void k_gather(const float* __restrict__ feat,
                                                int use_h1) {
    int node = blockIdx.x * 8 + (threadIdx.x >> 5);
    if (node >= NN) return;
    int lane = threadIdx.x & 31;
    const float* f = use_h1 ? g_h1 : feat;
    int beg = g_rowptr[node], end = g_rowptr[node + 1];
    float4 acc = make_float4(0.f, 0.f, 0.f, 0.f);
    int j = beg;
    for (; j + 3 < end; j += 4) {
        int s0 = g_col[j], s1 = g_col[j + 1], s2 = g_col[j + 2], s3 = g_col[j + 3];
        float4 v0 = reinterpret_cast<const float4*>(f + (size_t)s0 * D)[lane];
        float4 v1 = reinterpret_cast<const float4*>(f + (size_t)s1 * D)[lane];
        float4 v2 = reinterpret_cast<const float4*>(f + (size_t)s2 * D)[lane];
        float4 v3 = reinterpret_cast<const float4*>(f + (size_t)s3 * D)[lane];
        acc.x += (v0.x + v1.x) + (v2.x + v3.x);
        acc.y += (v0.y + v1.y) + (v2.y + v3.y);
        acc.z += (v0.z + v1.z) + (v2.z + v3.z);
        acc.w += (v0.w + v1.w) + (v2.w + v3.w);
    }
    for (; j < end; j++) {
        int s0 = g_col[j];
        float4 v0 = reinterpret_cast<const float4*>(f + (size_t)s0 * D)[lane];
        acc.x += v0.x; acc.y += v0.y; acc.z += v0.z; acc.w += v0.w;
    }
    float inv = 1.0f / fmaxf((float)(end - beg), 1.0f);
    acc.x *= inv; acc.y *= inv; acc.z *= inv; acc.w *= inv;
    reinterpret_cast<float4*>(g_agg + (size_t)node * D)[lane] = acc;
}

// ---------------------------------------------------------------------------
// tf32 tensor-core fused SAGE GEMM:
//   out = relu( mean @ Wl + x @ Wr + b ),  A = [g_agg | x_or_h1], W = [Wl;Wr]
// BM=128 rows/block, BN=128, BK=32 (8 k-blocks, 16 syncs), 8 warps,
// warp tile 64x32. SMEM stride 36: fragment bank = (4*grp + tig) % 32,
// all 32 lanes distinct -> conflict-free.
// ---------------------------------------------------------------------------
__device__ __forceinline__ uint32_t to_tf32(float f) {
    uint32_t r;
    asm("cvt.rna.tf32.f32 %0, %1;" : "=r"(r) : "f"(f));
    return r;
}

__global__ __launch_bounds__(256) void k_gemm(
    const float* __restrict__ xin,
    const float* __restrict__ Wl,
    const float* __restrict__ Wr,
    const float* __restrict__ bias,
    float* __restrict__ outbuf,
    int in_from_h1, int out_to_h1)
{
    __shared__ uint32_t As[128][36];
    __shared__ uint32_t Bs[128][36];

    const int tid  = threadIdx.x;
    const int wid  = tid >> 5;
    const int lane = tid & 31;
    const int grp  = lane >> 2;
    const int tig  = lane & 3;
    const int warpRow = (wid >> 2) * 64;
    const int warpCol = (wid & 3) * 32;
    const int rowBase = blockIdx.x * BM;
    const float* xsrc = in_from_h1 ? g_h1 : xin;

    float acc[4][4][4];
#pragma unroll
    for (int mt = 0; mt < 4; mt++)
#pragma unroll
        for (int nt = 0; nt < 4; nt++)
#pragma unroll
            for (int q = 0; q < 4; q++) acc[mt][nt][q] = 0.f;

    const int arow  = tid >> 1;          // 2 threads per row
    const int akloc = (tid & 1) * 16;    // each covers 16 k (4 float4)

    for (int kb = 0; kb < KDIM / 32; kb++) {
        const int k0 = kb * 32;

        // ---- stage A (128 rows x 32 k); 128%32==0 -> no source straddle
        {
            int grow = rowBase + arow;
            const float* srcp;
            if (grow < NN) {
                int kg = k0 + akloc;
                srcp = (k0 < D) ? &g_agg[(size_t)grow * D + kg]
                                : &xsrc[(size_t)grow * D + (kg - D)];
                uint2* dstp = reinterpret_cast<uint2*>(&As[arow][akloc]);
#pragma unroll
                for (int q = 0; q < 4; q++) {
                    float4 u = reinterpret_cast<const float4*>(srcp)[q];
                    dstp[2*q]   = make_uint2(to_tf32(u.x), to_tf32(u.y));
                    dstp[2*q+1] = make_uint2(to_tf32(u.z), to_tf32(u.w));
                }
            } else {
                uint2* dstp = reinterpret_cast<uint2*>(&As[arow][akloc]);
#pragma unroll
                for (int q = 0; q < 8; q++) dstp[q] = make_uint2(0u, 0u);
            }
        }

        // ---- stage B transposed: Bs[col][k] from W[k][col]
#pragma unroll
        for (int it = 0; it < 4; it++) {
            int lin = tid + it * 256;        // 0..1023
            int kk  = lin >> 5;              // 0..31
            int c4  = (lin & 31) * 4;        // 0..124
            int kg  = k0 + kk;
            const float* wsrc = (kg < D) ? (Wl + (size_t)kg * D + c4)
                                         : (Wr + (size_t)(kg - D) * D + c4);
            float4 u = *reinterpret_cast<const float4*>(wsrc);
            Bs[c4 + 0][kk] = to_tf32(u.x);
            Bs[c4 + 1][kk] = to_tf32(u.y);
            Bs[c4 + 2][kk] = to_tf32(u.z);
            Bs[c4 + 3][kk] = to_tf32(u.w);
        }
        __syncthreads();

#pragma unroll
        for (int ks = 0; ks < 4; ks++) {
            const int kb8 = ks * 8;
            uint32_t a[4][4], b[4][2];
#pragma unroll
            for (int mt = 0; mt < 4; mt++) {
                int r0 = warpRow + mt * 16;
                a[mt][0] = As[r0 + grp    ][kb8 + tig];
                a[mt][1] = As[r0 + grp + 8][kb8 + tig];
                a[mt][2] = As[r0 + grp    ][kb8 + tig + 4];
                a[mt][3] = As[r0 + grp + 8][kb8 + tig + 4];
            }
#pragma unroll
            for (int nt = 0; nt < 4; nt++) {
                int cn = warpCol + nt * 8 + grp;
                b[nt][0] = Bs[cn][kb8 + tig];
                b[nt][1] = Bs[cn][kb8 + tig + 4];
            }
#pragma unroll
            for (int mt = 0; mt < 4; mt++)
#pragma unroll
                for (int nt = 0; nt < 4; nt++) {
                    asm volatile(
                        "mma.sync.aligned.m16n8k8.row.col.f32.tf32.tf32.f32 "
                        "{%0,%1,%2,%3}, {%4,%5,%6,%7}, {%8,%9}, {%0,%1,%2,%3};\n"
                        : "+f"(acc[mt][nt][0]), "+f"(acc[mt][nt][1]),
                          "+f"(acc[mt][nt][2]), "+f"(acc[mt][nt][3])
                        : "r"(a[mt][0]), "r"(a[mt][1]), "r"(a[mt][2]), "r"(a[mt][3]),
                          "r"(b[nt][0]), "r"(b[nt][1]));
                }
        }
        __syncthreads();
    }

    float* o = out_to_h1 ? g_h1 : outbuf;
#pragma unroll
    for (int nt = 0; nt < 4; nt++) {
        int c = warpCol + nt * 8 + 2 * tig;
        float b0 = bias[c], b1 = bias[c + 1];
#pragma unroll
        for (int mt = 0; mt < 4; mt++) {
            int r = rowBase + warpRow + mt * 16 + grp;
            if (r < NN) {
                float2 v;
                v.x = fmaxf(acc[mt][nt][0] + b0, 0.f);
                v.y = fmaxf(acc[mt][nt][1] + b1, 0.f);
                *reinterpret_cast<float2*>(&o[(size_t)r * D + c]) = v;
            }
            if (r + 8 < NN) {
                float2 v;
                v.x = fmaxf(acc[mt][nt][2] + b0, 0.f);
                v.y = fmaxf(acc[mt][nt][3] + b1, 0.f);
                *reinterpret_cast<float2*>(&o[(size_t)(r + 8) * D + c]) = v;
            }
        }
    }
}

// ---------------------------------------------------------------------------
// kernel_launch: init -> hist -> scan x3 -> fill -> gather1 -> gemm1 ->
//                gather2 -> gemm2
// ---------------------------------------------------------------------------
extern "C" void kernel_launch(void* const* d_in, const int* in_sizes, int n_in,
                              void* d_out, int out_size) {
    const float* x   = (const float*)d_in[0];
    const void*  ei  = d_in[1];
    const float* W1l = (const float*)d_in[2];
    const float* b1  = (const float*)d_in[3];
    const float* W1r = (const float*)d_in[4];
    const float* W2l = (const float*)d_in[5];
    const float* b2  = (const float*)d_in[6];
    const float* W2r = (const float*)d_in[7];
    float*       out = (float*)d_out;

    const int E = in_sizes[1] / 2;
    const int eblocks = (E + 255) / 256;
    const int gemmBlocks = (NN + BM - 1) / BM;
    const int gatherBlocks = (NN + 7) / 8;

    k_init<<<SCAN_BLOCKS, 256>>>((const int*)ei, in_sizes[1]);

    // CSR build (reads edge index directly; no decode pass)
    k_hist<<<eblocks, 256>>>(ei, E);
    k_scan1<<<SCAN_BLOCKS, 256>>>();
    k_scan2<<<1, 256>>>(SCAN_BLOCKS);
    k_scan3<<<SCAN_BLOCKS, 256>>>(E);
    k_fill<<<eblocks, 256>>>(ei, E);

    // Layer 1
    k_gather<<<gatherBlocks, 256>>>(x, 0);
    k_gemm<<<gemmBlocks, 256>>>(x, W1l, W1r, b1, out, 0, 1);   // -> g_h1

    // Layer 2
    k_gather<<<gatherBlocks, 256>>>(x /*unused*/, 1);          // reads g_h1
    k_gemm<<<gemmBlocks, 256>>>(x /*unused*/, W2l, W2r, b2, out, 1, 0);
}

// round 8
// speedup vs baseline: 1.2314x; 1.0428x over previous
#include <cuda_runtime.h>
#include <cuda_fp16.h>
#include <cstdint>

#define NN 50000
#define D  128
#define KDIM 256
#define BM 128
#define EMAX 640000
#define SCAN_BLOCKS 196   // ceil(50000/256)

// Scratch: __device__ globals (no allocation allowed).
__device__ __align__(128) float  g_agg[(size_t)NN * D];   // MEAN (fp32)
__device__ __align__(128) __half g_xh [(size_t)NN * D];   // x in fp16
__device__ __align__(128) __half g_h1h[(size_t)NN * D];   // h1 in fp16
__device__ __align__(128) int    g_cnt[NN];
__device__ __align__(128) int    g_rowptr[NN + 1];
__device__ __align__(128) int    g_col[EMAX];
__device__ __align__(128) int    g_bsum[256];
__device__ int g_is64;

// ---------------------------------------------------------------------------
// Init: zero g_cnt; block 0 probes edge_index dtype (int64 ids < 2^31 ->
// all odd 32-bit words zero).
// ---------------------------------------------------------------------------
__global__ void k_init(const int* __restrict__ ei32, int n32) {
    int gid = blockIdx.x * 256 + threadIdx.x;
    if (gid < NN) g_cnt[gid] = 0;
    if (blockIdx.x == 0) {
        __shared__ int any_nz;
        if (threadIdx.x == 0) any_nz = 0;
        __syncthreads();
        int limit = n32 < 8192 ? n32 : 8192;
        int found = 0;
        for (int i = threadIdx.x * 2 + 1; i < limit; i += 512)
            if (ei32[i] != 0) { found = 1; break; }
        if (found) atomicOr(&any_nz, 1);
        __syncthreads();
        if (threadIdx.x == 0) g_is64 = any_nz ? 0 : 1;
    }
}

__device__ __forceinline__ int eidx(const void* ei, int i) {
    return g_is64 ? (int)((const long long*)ei)[i] : ((const int*)ei)[i];
}

// x (fp32) -> g_xh (fp16), 8 elems/thread.
__global__ void k_tohalf(const float* __restrict__ x) {
    long long i = (long long)blockIdx.x * blockDim.x + threadIdx.x;
    long long tot8 = (long long)NN * D / 8;
    if (i >= tot8) return;
    const float4* p = reinterpret_cast<const float4*>(x) + i * 2;
    float4 a = p[0], b = p[1];
    __half2 h0 = __floats2half2_rn(a.x, a.y);
    __half2 h1 = __floats2half2_rn(a.z, a.w);
    __half2 h2 = __floats2half2_rn(b.x, b.y);
    __half2 h3 = __floats2half2_rn(b.z, b.w);
    uint4 o;
    o.x = *reinterpret_cast<uint32_t*>(&h0);
    o.y = *reinterpret_cast<uint32_t*>(&h1);
    o.z = *reinterpret_cast<uint32_t*>(&h2);
    o.w = *reinterpret_cast<uint32_t*>(&h3);
    reinterpret_cast<uint4*>(g_xh)[i] = o;
}

__global__ void k_hist(const void* __restrict__ ei, int E) {
    int e = blockIdx.x * blockDim.x + threadIdx.x;
    if (e < E) atomicAdd(&g_cnt[eidx(ei, E + e)], 1);
}

// Stage 1: per-block exclusive scan, publish block sums.
__global__ void k_scan1() {
    __shared__ int sh[256];
    int gid = blockIdx.x * 256 + threadIdx.x;
    int v = (gid < NN) ? g_cnt[gid] : 0;
    sh[threadIdx.x] = v;
    __syncthreads();
    for (int off = 1; off < 256; off <<= 1) {
        int t = (threadIdx.x >= off) ? sh[threadIdx.x - off] : 0;
        __syncthreads();
        sh[threadIdx.x] += t;
        __syncthreads();
    }
    if (gid < NN) g_rowptr[gid] = sh[threadIdx.x] - v;
    if (threadIdx.x == 255) g_bsum[blockIdx.x] = sh[255];
}

// Stage 2 (fused scan2+scan3): each block REDUCES preceding block sums
// (needs only the sum, not a scan) and applies the offset.
__global__ void k_scan3(int E) {
    __shared__ int sh[256];
    int t = threadIdx.x;
    sh[t] = (t < blockIdx.x) ? g_bsum[t] : 0;   // blockIdx.x < 196 < 256
    __syncthreads();
    for (int off = 128; off > 0; off >>= 1) {
        if (t < off) sh[t] += sh[t + off];
        __syncthreads();
    }
    int base = sh[0];
    int gid = blockIdx.x * 256 + t;
    if (gid < NN) {
        int r = g_rowptr[gid] + base;
        g_rowptr[gid] = r;
        g_cnt[gid] = r;          // cursor for fill
    }
    if (gid == 0) g_rowptr[NN] = E;
}

__global__ void k_fill(const void* __restrict__ ei, int E) {
    int e = blockIdx.x * blockDim.x + threadIdx.x;
    if (e < E) {
        int s = eidx(ei, e);
        int d = eidx(ei, E + e);
        int idx = atomicAdd(&g_cnt[d], 1);
        g_col[idx] = s;
    }
}

// ---------------------------------------------------------------------------
// CSR gather over fp16 features, fp32 accumulation. One warp per node.
// fp16 row = 256B = 16 lanes x uint4: half-warp h handles edges of parity h,
// unrolled x4 -> 8 edges in flight per warp (LDG.128, MLP 8). Half-warp
// partial sums combined via shfl_xor(16); lanes 0-15 write the mean.
// ---------------------------------------------------------------------------
__global__ __launch_bounds__(256) void k_gather(int use_h1) {
    int node = blockIdx.x * 8 + (threadIdx.x >> 5);
    if (node >= NN) return;
    int lane = threadIdx.x & 31;
    int half = lane >> 4;     // 0/1: edge parity
    int li   = lane & 15;     // owns 8 halves = 16B of the row
    const __half* f = use_h1 ? g_h1h : g_xh;
    int beg = g_rowptr[node], end = g_rowptr[node + 1];

    float acc[8];
#pragma unroll
    for (int q = 0; q < 8; q++) acc[q] = 0.f;

    int j = beg + half;
    for (; j + 6 < end; j += 8) {
        int s0 = g_col[j], s1 = g_col[j + 2], s2 = g_col[j + 4], s3 = g_col[j + 6];
        uint4 u0 = reinterpret_cast<const uint4*>(f + (size_t)s0 * D)[li];
        uint4 u1 = reinterpret_cast<const uint4*>(f + (size_t)s1 * D)[li];
        uint4 u2 = reinterpret_cast<const uint4*>(f + (size_t)s2 * D)[li];
        uint4 u3 = reinterpret_cast<const uint4*>(f + (size_t)s3 * D)[li];
#pragma unroll
        for (int w = 0; w < 4; w++) {
            uint32_t c0 = (&u0.x)[w], c1 = (&u1.x)[w], c2 = (&u2.x)[w], c3 = (&u3.x)[w];
            float2 f0 = __half22float2(*reinterpret_cast<__half2*>(&c0));
            float2 f1 = __half22float2(*reinterpret_cast<__half2*>(&c1));
            float2 f2 = __half22float2(*reinterpret_cast<__half2*>(&c2));
            float2 f3 = __half22float2(*reinterpret_cast<__half2*>(&c3));
            acc[2*w]   += (f0.x + f1.x) + (f2.x + f3.x);
            acc[2*w+1] += (f0.y + f1.y) + (f2.y + f3.y);
        }
    }
    for (; j < end; j += 2) {
        int s0 = g_col[j];
        uint4 u0 = reinterpret_cast<const uint4*>(f + (size_t)s0 * D)[li];
#pragma unroll
        for (int w = 0; w < 4; w++) {
            uint32_t c0 = (&u0.x)[w];
            float2 f0 = __half22float2(*reinterpret_cast<__half2*>(&c0));
            acc[2*w]   += f0.x;
            acc[2*w+1] += f0.y;
        }
    }
    // combine the two half-warp partial sums
#pragma unroll
    for (int q = 0; q < 8; q++)
        acc[q] += __shfl_xor_sync(0xffffffffu, acc[q], 16);

    if (half == 0) {
        float inv = 1.0f / fmaxf((float)(end - beg), 1.0f);
        float* o = g_agg + (size_t)node * D + li * 8;
        float4 r0 = make_float4(acc[0]*inv, acc[1]*inv, acc[2]*inv, acc[3]*inv);
        float4 r1 = make_float4(acc[4]*inv, acc[5]*inv, acc[6]*inv, acc[7]*inv);
        reinterpret_cast<float4*>(o)[0] = r0;
        reinterpret_cast<float4*>(o)[1] = r1;
    }
}

// ---------------------------------------------------------------------------
// tf32 tensor-core fused SAGE GEMM:
//   out = relu( mean @ Wl + feat @ Wr + b ),  A = [g_agg fp32 | feat fp16]
// BM=128, BN=128, BK=32, 8 warps, warp tile 64x32; SMEM stride 36
// (bank = (4*grp+tig)%32, conflict-free). Epilogue: fp16 -> g_h1h (layer 1)
// or fp32 -> outbuf (layer 2).
// ---------------------------------------------------------------------------
__device__ __forceinline__ uint32_t to_tf32(float f) {
    uint32_t r;
    asm("cvt.rna.tf32.f32 %0, %1;" : "=r"(r) : "f"(f));
    return r;
}

__global__ __launch_bounds__(256) void k_gemm(
    const float* __restrict__ Wl,
    const float* __restrict__ Wr,
    const float* __restrict__ bias,
    float* __restrict__ outbuf,
    int in_from_h1, int out_to_h1)
{
    __shared__ uint32_t As[128][36];
    __shared__ uint32_t Bs[128][36];

    const int tid  = threadIdx.x;
    const int wid  = tid >> 5;
    const int lane = tid & 31;
    const int grp  = lane >> 2;
    const int tig  = lane & 3;
    const int warpRow = (wid >> 2) * 64;
    const int warpCol = (wid & 3) * 32;
    const int rowBase = blockIdx.x * BM;
    const __half* xh = in_from_h1 ? g_h1h : g_xh;

    float acc[4][4][4];
#pragma unroll
    for (int mt = 0; mt < 4; mt++)
#pragma unroll
        for (int nt = 0; nt < 4; nt++)
#pragma unroll
            for (int q = 0; q < 4; q++) acc[mt][nt][q] = 0.f;

    const int arow  = tid >> 1;          // 2 threads per row
    const int akloc = (tid & 1) * 16;    // each covers 16 k

    for (int kb = 0; kb < KDIM / 32; kb++) {
        const int k0 = kb * 32;

        // ---- stage A (128 rows x 32 k); k0<128 -> g_agg (fp32), else fp16
        {
            int grow = rowBase + arow;
            uint2* dstp = reinterpret_cast<uint2*>(&As[arow][akloc]);
            if (grow < NN) {
                int kg = k0 + akloc;
                if (k0 < D) {
                    const float4* p = reinterpret_cast<const float4*>(
                        &g_agg[(size_t)grow * D + kg]);
#pragma unroll
                    for (int q = 0; q < 4; q++) {
                        float4 u = p[q];
                        dstp[2*q]   = make_uint2(to_tf32(u.x), to_tf32(u.y));
                        dstp[2*q+1] = make_uint2(to_tf32(u.z), to_tf32(u.w));
                    }
                } else {
                    const uint4* p = reinterpret_cast<const uint4*>(
                        &xh[(size_t)grow * D + (kg - D)]);
#pragma unroll
                    for (int q = 0; q < 2; q++) {
                        uint4 u = p[q];
#pragma unroll
                        for (int w = 0; w < 4; w++) {
                            uint32_t c = (&u.x)[w];
                            float2 fv = __half22float2(*reinterpret_cast<__half2*>(&c));
                            dstp[4*q + w] = make_uint2(to_tf32(fv.x), to_tf32(fv.y));
                        }
                    }
                }
            } else {
#pragma unroll
                for (int q = 0; q < 8; q++) dstp[q] = make_uint2(0u, 0u);
            }
        }

        // ---- stage B transposed: Bs[col][k] from W[k][col]
#pragma unroll
        for (int it = 0; it < 4; it++) {
            int lin = tid + it * 256;
            int kk  = lin >> 5;
            int c4  = (lin & 31) * 4;
            int kg  = k0 + kk;
            const float* wsrc = (kg < D) ? (Wl + (size_t)kg * D + c4)
                                         : (Wr + (size_t)(kg - D) * D + c4);
            float4 u = *reinterpret_cast<const float4*>(wsrc);
            Bs[c4 + 0][kk] = to_tf32(u.x);
            Bs[c4 + 1][kk] = to_tf32(u.y);
            Bs[c4 + 2][kk] = to_tf32(u.z);
            Bs[c4 + 3][kk] = to_tf32(u.w);
        }
        __syncthreads();

#pragma unroll
        for (int ks = 0; ks < 4; ks++) {
            const int kb8 = ks * 8;
            uint32_t a[4][4], b[4][2];
#pragma unroll
            for (int mt = 0; mt < 4; mt++) {
                int r0 = warpRow + mt * 16;
                a[mt][0] = As[r0 + grp    ][kb8 + tig];
                a[mt][1] = As[r0 + grp + 8][kb8 + tig];
                a[mt][2] = As[r0 + grp    ][kb8 + tig + 4];
                a[mt][3] = As[r0 + grp + 8][kb8 + tig + 4];
            }
#pragma unroll
            for (int nt = 0; nt < 4; nt++) {
                int cn = warpCol + nt * 8 + grp;
                b[nt][0] = Bs[cn][kb8 + tig];
                b[nt][1] = Bs[cn][kb8 + tig + 4];
            }
#pragma unroll
            for (int mt = 0; mt < 4; mt++)
#pragma unroll
                for (int nt = 0; nt < 4; nt++) {
                    asm volatile(
                        "mma.sync.aligned.m16n8k8.row.col.f32.tf32.tf32.f32 "
                        "{%0,%1,%2,%3}, {%4,%5,%6,%7}, {%8,%9}, {%0,%1,%2,%3};\n"
                        : "+f"(acc[mt][nt][0]), "+f"(acc[mt][nt][1]),
                          "+f"(acc[mt][nt][2]), "+f"(acc[mt][nt][3])
                        : "r"(a[mt][0]), "r"(a[mt][1]), "r"(a[mt][2]), "r"(a[mt][3]),
                          "r"(b[nt][0]), "r"(b[nt][1]));
                }
        }
        __syncthreads();
    }

    // ---- epilogue
#pragma unroll
    for (int nt = 0; nt < 4; nt++) {
        int c = warpCol + nt * 8 + 2 * tig;
        float b0 = bias[c], b1 = bias[c + 1];
#pragma unroll
        for (int mt = 0; mt < 4; mt++) {
            int r = rowBase + warpRow + mt * 16 + grp;
            float v0 = fmaxf(acc[mt][nt][0] + b0, 0.f);
            float v1 = fmaxf(acc[mt][nt][1] + b1, 0.f);
            float v2 = fmaxf(acc[mt][nt][2] + b0, 0.f);
            float v3 = fmaxf(acc[mt][nt][3] + b1, 0.f);
            if (out_to_h1) {
                if (r < NN)
                    *reinterpret_cast<__half2*>(&g_h1h[(size_t)r * D + c]) =
                        __floats2half2_rn(v0, v1);
                if (r + 8 < NN)
                    *reinterpret_cast<__half2*>(&g_h1h[(size_t)(r + 8) * D + c]) =
                        __floats2half2_rn(v2, v3);
            } else {
                if (r < NN)
                    *reinterpret_cast<float2*>(&outbuf[(size_t)r * D + c]) =
                        make_float2(v0, v1);
                if (r + 8 < NN)
                    *reinterpret_cast<float2*>(&outbuf[(size_t)(r + 8) * D + c]) =
                        make_float2(v2, v3);
            }
        }
    }
}

// ---------------------------------------------------------------------------
extern "C" void kernel_launch(void* const* d_in, const int* in_sizes, int n_in,
                              void* d_out, int out_size) {
    const float* x   = (const float*)d_in[0];
    const void*  ei  = d_in[1];
    const float* W1l = (const float*)d_in[2];
    const float* b1  = (const float*)d_in[3];
    const float* W1r = (const float*)d_in[4];
    const float* W2l = (const float*)d_in[5];
    const float* b2  = (const float*)d_in[6];
    const float* W2r = (const float*)d_in[7];
    float*       out = (float*)d_out;

    const int E = in_sizes[1] / 2;
    const int eblocks = (E + 255) / 256;
    const int gemmBlocks = (NN + BM - 1) / BM;
    const int gatherBlocks = (NN + 7) / 8;
    const int halfBlocks = (int)(((long long)NN * D / 8 + 255) / 256);

    k_init<<<SCAN_BLOCKS, 256>>>((const int*)ei, in_sizes[1]);
    k_tohalf<<<halfBlocks, 256>>>(x);

    // CSR build
    k_hist<<<eblocks, 256>>>(ei, E);
    k_scan1<<<SCAN_BLOCKS, 256>>>();
    k_scan3<<<SCAN_BLOCKS, 256>>>(E);
    k_fill<<<eblocks, 256>>>(ei, E);

    // Layer 1
    k_gather<<<gatherBlocks, 256>>>(0);
    k_gemm<<<gemmBlocks, 256>>>(W1l, W1r, b1, out, 0, 1);   // -> g_h1h (fp16)

    // Layer 2
    k_gather<<<gatherBlocks, 256>>>(1);
    k_gemm<<<gemmBlocks, 256>>>(W2l, W2r, b2, out, 1, 0);   // -> d_out
}

// round 9
// speedup vs baseline: 1.2568x; 1.0206x over previous
#include <cuda_runtime.h>
#include <cuda_fp16.h>
#include <cstdint>

#define NN 50000
#define D  128
#define KDIM 256
#define BM 128
#define EMAX 640000
#define SCAN_BLOCKS 196   // ceil(50000/256)

// Scratch: __device__ globals (no allocation allowed).
__device__ __align__(128) float  g_agg[(size_t)NN * D];   // MEAN (fp32)
__device__ __align__(128) __half g_xh [(size_t)NN * D];   // x in fp16
__device__ __align__(128) __half g_h1h[(size_t)NN * D];   // h1 in fp16
__device__ __align__(128) int    g_cnt[NN];
__device__ __align__(128) int    g_rowptr[NN + 1];
__device__ __align__(128) int    g_col[EMAX];
__device__ __align__(128) int    g_bsum[256];
__device__ int g_is64;

// ---------------------------------------------------------------------------
// Fused init: zero g_cnt, convert x -> fp16, block 0 probes edge dtype
// (int64 ids < 2^31 -> all odd 32-bit words zero). Grid sized for tohalf.
// ---------------------------------------------------------------------------
__global__ void k_init(const float* __restrict__ x,
                       const int* __restrict__ ei32, int n32) {
    long long i = (long long)blockIdx.x * 256 + threadIdx.x;
    if (i < NN) g_cnt[(int)i] = 0;

    long long tot8 = (long long)NN * D / 8;
    if (i < tot8) {
        const float4* p = reinterpret_cast<const float4*>(x) + i * 2;
        float4 a = p[0], b = p[1];
        __half2 h0 = __floats2half2_rn(a.x, a.y);
        __half2 h1 = __floats2half2_rn(a.z, a.w);
        __half2 h2 = __floats2half2_rn(b.x, b.y);
        __half2 h3 = __floats2half2_rn(b.z, b.w);
        uint4 o;
        o.x = *reinterpret_cast<uint32_t*>(&h0);
        o.y = *reinterpret_cast<uint32_t*>(&h1);
        o.z = *reinterpret_cast<uint32_t*>(&h2);
        o.w = *reinterpret_cast<uint32_t*>(&h3);
        reinterpret_cast<uint4*>(g_xh)[i] = o;
    }

    if (blockIdx.x == 0) {
        __shared__ int any_nz;
        if (threadIdx.x == 0) any_nz = 0;
        __syncthreads();
        int limit = n32 < 8192 ? n32 : 8192;
        int found = 0;
        for (int k = threadIdx.x * 2 + 1; k < limit; k += 512)
            if (ei32[k] != 0) { found = 1; break; }
        if (found) atomicOr(&any_nz, 1);
        __syncthreads();
        if (threadIdx.x == 0) g_is64 = any_nz ? 0 : 1;
    }
}

// Low-word-only index read (node ids < 2^31: high word of int64 is zero).
__device__ __forceinline__ int eidx(const void* ei, int i) {
    return g_is64 ? ((const int*)ei)[2 * i] : ((const int*)ei)[i];
}

__global__ void k_hist(const void* __restrict__ ei, int E) {
    int e = blockIdx.x * blockDim.x + threadIdx.x;
    if (e < E) atomicAdd(&g_cnt[eidx(ei, E + e)], 1);
}

// Stage 1: per-block exclusive scan, publish block sums.
__global__ void k_scan1() {
    __shared__ int sh[256];
    int gid = blockIdx.x * 256 + threadIdx.x;
    int v = (gid < NN) ? g_cnt[gid] : 0;
    sh[threadIdx.x] = v;
    __syncthreads();
    for (int off = 1; off < 256; off <<= 1) {
        int t = (threadIdx.x >= off) ? sh[threadIdx.x - off] : 0;
        __syncthreads();
        sh[threadIdx.x] += t;
        __syncthreads();
    }
    if (gid < NN) g_rowptr[gid] = sh[threadIdx.x] - v;
    if (threadIdx.x == 255) g_bsum[blockIdx.x] = sh[255];
}

// Stage 2: each block reduces preceding block sums and applies offset.
__global__ void k_scan3(int E) {
    __shared__ int sh[256];
    int t = threadIdx.x;
    sh[t] = (t < blockIdx.x) ? g_bsum[t] : 0;
    __syncthreads();
    for (int off = 128; off > 0; off >>= 1) {
        if (t < off) sh[t] += sh[t + off];
        __syncthreads();
    }
    int base = sh[0];
    int gid = blockIdx.x * 256 + t;
    if (gid < NN) {
        int r = g_rowptr[gid] + base;
        g_rowptr[gid] = r;
        g_cnt[gid] = r;          // cursor for fill
    }
    if (gid == 0) g_rowptr[NN] = E;
}

__global__ void k_fill(const void* __restrict__ ei, int E) {
    int e = blockIdx.x * blockDim.x + threadIdx.x;
    if (e < E) {
        int s = eidx(ei, e);
        int d = eidx(ei, E + e);
        int idx = atomicAdd(&g_cnt[d], 1);
        g_col[idx] = s;
    }
}

// ---------------------------------------------------------------------------
// CSR gather over fp16 features, fp32 accumulation. One warp per node.
// fp16 row = 256B = 16 lanes x uint4. Half-warp h handles edges of parity h,
// 4 at a time with PREDICATED tail (clamped index + 0/1 mask) so every node
// completes in ceil(cnt/8) fully-pipelined iterations (MLP 8 per warp, no
// serial remainder). Half-warp sums combined via shfl_xor(16).
// ---------------------------------------------------------------------------
__global__ __launch_bounds__(256) void k_gather(int use_h1) {
    int node = blockIdx.x * 8 + (threadIdx.x >> 5);
    if (node >= NN) return;
    int lane = threadIdx.x & 31;
    int half = lane >> 4;     // 0/1: edge parity
    int li   = lane & 15;     // owns 8 halves = 16B of the row
    const __half* f = use_h1 ? g_h1h : g_xh;
    int beg = g_rowptr[node], end = g_rowptr[node + 1];

    float acc[8];
#pragma unroll
    for (int q = 0; q < 8; q++) acc[q] = 0.f;

    if (beg < end) {
        for (int j = beg + half; j < end; j += 8) {
            int i1 = j + 2, i2 = j + 4, i3 = j + 6;
            // j < end guaranteed; clamp the rest (beg is always valid).
            int s0 = g_col[j];
            int s1 = g_col[i1 < end ? i1 : beg];
            int s2 = g_col[i2 < end ? i2 : beg];
            int s3 = g_col[i3 < end ? i3 : beg];
            float m1 = i1 < end ? 1.f : 0.f;
            float m2 = i2 < end ? 1.f : 0.f;
            float m3 = i3 < end ? 1.f : 0.f;
            uint4 u0 = reinterpret_cast<const uint4*>(f + (size_t)s0 * D)[li];
            uint4 u1 = reinterpret_cast<const uint4*>(f + (size_t)s1 * D)[li];
            uint4 u2 = reinterpret_cast<const uint4*>(f + (size_t)s2 * D)[li];
            uint4 u3 = reinterpret_cast<const uint4*>(f + (size_t)s3 * D)[li];
#pragma unroll
            for (int w = 0; w < 4; w++) {
                uint32_t c0 = (&u0.x)[w], c1 = (&u1.x)[w];
                uint32_t c2 = (&u2.x)[w], c3 = (&u3.x)[w];
                float2 f0 = __half22float2(*reinterpret_cast<__half2*>(&c0));
                float2 f1 = __half22float2(*reinterpret_cast<__half2*>(&c1));
                float2 f2 = __half22float2(*reinterpret_cast<__half2*>(&c2));
                float2 f3 = __half22float2(*reinterpret_cast<__half2*>(&c3));
                acc[2*w]   += f0.x + m1 * f1.x + m2 * f2.x + m3 * f3.x;
                acc[2*w+1] += f0.y + m1 * f1.y + m2 * f2.y + m3 * f3.y;
            }
        }
    }
#pragma unroll
    for (int q = 0; q < 8; q++)
        acc[q] += __shfl_xor_sync(0xffffffffu, acc[q], 16);

    if (half == 0) {
        float inv = 1.0f / fmaxf((float)(end - beg), 1.0f);
        float* o = g_agg + (size_t)node * D + li * 8;
        reinterpret_cast<float4*>(o)[0] =
            make_float4(acc[0]*inv, acc[1]*inv, acc[2]*inv, acc[3]*inv);
        reinterpret_cast<float4*>(o)[1] =
            make_float4(acc[4]*inv, acc[5]*inv, acc[6]*inv, acc[7]*inv);
    }
}

// ---------------------------------------------------------------------------
// tf32 tensor-core fused SAGE GEMM (unchanged from R8):
//   out = relu( mean @ Wl + feat @ Wr + b ),  A = [g_agg fp32 | feat fp16]
// ---------------------------------------------------------------------------
__device__ __forceinline__ uint32_t to_tf32(float f) {
    uint32_t r;
    asm("cvt.rna.tf32.f32 %0, %1;" : "=r"(r) : "f"(f));
    return r;
}

__global__ __launch_bounds__(256) void k_gemm(
    const float* __restrict__ Wl,
    const float* __restrict__ Wr,
    const float* __restrict__ bias,
    float* __restrict__ outbuf,
    int in_from_h1, int out_to_h1)
{
    __shared__ uint32_t As[128][36];
    __shared__ uint32_t Bs[128][36];

    const int tid  = threadIdx.x;
    const int wid  = tid >> 5;
    const int lane = tid & 31;
    const int grp  = lane >> 2;
    const int tig  = lane & 3;
    const int warpRow = (wid >> 2) * 64;
    const int warpCol = (wid & 3) * 32;
    const int rowBase = blockIdx.x * BM;
    const __half* xh = in_from_h1 ? g_h1h : g_xh;

    float acc[4][4][4];
#pragma unroll
    for (int mt = 0; mt < 4; mt++)
#pragma unroll
        for (int nt = 0; nt < 4; nt++)
#pragma unroll
            for (int q = 0; q < 4; q++) acc[mt][nt][q] = 0.f;

    const int arow  = tid >> 1;
    const int akloc = (tid & 1) * 16;

    for (int kb = 0; kb < KDIM / 32; kb++) {
        const int k0 = kb * 32;

        // ---- stage A
        {
            int grow = rowBase + arow;
            uint2* dstp = reinterpret_cast<uint2*>(&As[arow][akloc]);
            if (grow < NN) {
                int kg = k0 + akloc;
                if (k0 < D) {
                    const float4* p = reinterpret_cast<const float4*>(
                        &g_agg[(size_t)grow * D + kg]);
#pragma unroll
                    for (int q = 0; q < 4; q++) {
                        float4 u = p[q];
                        dstp[2*q]   = make_uint2(to_tf32(u.x), to_tf32(u.y));
                        dstp[2*q+1] = make_uint2(to_tf32(u.z), to_tf32(u.w));
                    }
                } else {
                    const uint4* p = reinterpret_cast<const uint4*>(
                        &xh[(size_t)grow * D + (kg - D)]);
#pragma unroll
                    for (int q = 0; q < 2; q++) {
                        uint4 u = p[q];
#pragma unroll
                        for (int w = 0; w < 4; w++) {
                            uint32_t c = (&u.x)[w];
                            float2 fv = __half22float2(*reinterpret_cast<__half2*>(&c));
                            dstp[4*q + w] = make_uint2(to_tf32(fv.x), to_tf32(fv.y));
                        }
                    }
                }
            } else {
#pragma unroll
                for (int q = 0; q < 8; q++) dstp[q] = make_uint2(0u, 0u);
            }
        }

        // ---- stage B transposed
#pragma unroll
        for (int it = 0; it < 4; it++) {
            int lin = tid + it * 256;
            int kk  = lin >> 5;
            int c4  = (lin & 31) * 4;
            int kg  = k0 + kk;
            const float* wsrc = (kg < D) ? (Wl + (size_t)kg * D + c4)
                                         : (Wr + (size_t)(kg - D) * D + c4);
            float4 u = *reinterpret_cast<const float4*>(wsrc);
            Bs[c4 + 0][kk] = to_tf32(u.x);
            Bs[c4 + 1][kk] = to_tf32(u.y);
            Bs[c4 + 2][kk] = to_tf32(u.z);
            Bs[c4 + 3][kk] = to_tf32(u.w);
        }
        __syncthreads();

#pragma unroll
        for (int ks = 0; ks < 4; ks++) {
            const int kb8 = ks * 8;
            uint32_t a[4][4], b[4][2];
#pragma unroll
            for (int mt = 0; mt < 4; mt++) {
                int r0 = warpRow + mt * 16;
                a[mt][0] = As[r0 + grp    ][kb8 + tig];
                a[mt][1] = As[r0 + grp + 8][kb8 + tig];
                a[mt][2] = As[r0 + grp    ][kb8 + tig + 4];
                a[mt][3] = As[r0 + grp + 8][kb8 + tig + 4];
            }
#pragma unroll
            for (int nt = 0; nt < 4; nt++) {
                int cn = warpCol + nt * 8 + grp;
                b[nt][0] = Bs[cn][kb8 + tig];
                b[nt][1] = Bs[cn][kb8 + tig + 4];
            }
#pragma unroll
            for (int mt = 0; mt < 4; mt++)
#pragma unroll
                for (int nt = 0; nt < 4; nt++) {
                    asm volatile(
                        "mma.sync.aligned.m16n8k8.row.col.f32.tf32.tf32.f32 "
                        "{%0,%1,%2,%3}, {%4,%5,%6,%7}, {%8,%9}, {%0,%1,%2,%3};\n"
                        : "+f"(acc[mt][nt][0]), "+f"(acc[mt][nt][1]),
                          "+f"(acc[mt][nt][2]), "+f"(acc[mt][nt][3])
                        : "r"(a[mt][0]), "r"(a[mt][1]), "r"(a[mt][2]), "r"(a[mt][3]),
                          "r"(b[nt][0]), "r"(b[nt][1]));
                }
        }
        __syncthreads();
    }

    // ---- epilogue
#pragma unroll
    for (int nt = 0; nt < 4; nt++) {
        int c = warpCol + nt * 8 + 2 * tig;
        float b0 = bias[c], b1 = bias[c + 1];
#pragma unroll
        for (int mt = 0; mt < 4; mt++) {
            int r = rowBase + warpRow + mt * 16 + grp;
            float v0 = fmaxf(acc[mt][nt][0] + b0, 0.f);
            float v1 = fmaxf(acc[mt][nt][1] + b1, 0.f);
            float v2 = fmaxf(acc[mt][nt][2] + b0, 0.f);
            float v3 = fmaxf(acc[mt][nt][3] + b1, 0.f);
            if (out_to_h1) {
                if (r < NN)
                    *reinterpret_cast<__half2*>(&g_h1h[(size_t)r * D + c]) =
                        __floats2half2_rn(v0, v1);
                if (r + 8 < NN)
                    *reinterpret_cast<__half2*>(&g_h1h[(size_t)(r + 8) * D + c]) =
                        __floats2half2_rn(v2, v3);
            } else {
                if (r < NN)
                    *reinterpret_cast<float2*>(&outbuf[(size_t)r * D + c]) =
                        make_float2(v0, v1);
                if (r + 8 < NN)
                    *reinterpret_cast<float2*>(&outbuf[(size_t)(r + 8) * D + c]) =
                        make_float2(v2, v3);
            }
        }
    }
}

// ---------------------------------------------------------------------------
extern "C" void kernel_launch(void* const* d_in, const int* in_sizes, int n_in,
                              void* d_out, int out_size) {
    const float* x   = (const float*)d_in[0];
    const void*  ei  = d_in[1];
    const float* W1l = (const float*)d_in[2];
    const float* b1  = (const float*)d_in[3];
    const float* W1r = (const float*)d_in[4];
    const float* W2l = (const float*)d_in[5];
    const float* b2  = (const float*)d_in[6];
    const float* W2r = (const float*)d_in[7];
    float*       out = (float*)d_out;

    const int E = in_sizes[1] / 2;
    const int eblocks = (E + 255) / 256;
    const int gemmBlocks = (NN + BM - 1) / BM;
    const int gatherBlocks = (NN + 7) / 8;
    const int initBlocks = (int)(((long long)NN * D / 8 + 255) / 256);

    k_init<<<initBlocks, 256>>>(x, (const int*)ei, in_sizes[1]);

    // CSR build
    k_hist<<<eblocks, 256>>>(ei, E);
    k_scan1<<<SCAN_BLOCKS, 256>>>();
    k_scan3<<<SCAN_BLOCKS, 256>>>(E);
    k_fill<<<eblocks, 256>>>(ei, E);

    // Layer 1
    k_gather<<<gatherBlocks, 256>>>(0);
    k_gemm<<<gemmBlocks, 256>>>(W1l, W1r, b1, out, 0, 1);   // -> g_h1h (fp16)

    // Layer 2
    k_gather<<<gatherBlocks, 256>>>(1);
    k_gemm<<<gemmBlocks, 256>>>(W2l, W2r, b2, out, 1, 0);   // -> d_out
}